// round 1
// baseline (speedup 1.0000x reference)
#include <cuda_runtime.h>
#include <math.h>

#define Bdim 4
#define Sdim 2048
#define Hdim 768
#define NHdim 12
#define Ddim 64
#define ATT_SCALE 0.125f
#define LOG2E 1.4426950408889634f

// Scratch: Q/K/V in [B, NH, S, D] fp32. 25.2 MB each.
__device__ float g_Q[Bdim * NHdim * Sdim * Ddim];
__device__ float g_K[Bdim * NHdim * Sdim * Ddim];
__device__ float g_V[Bdim * NHdim * Sdim * Ddim];

// ---------------------------------------------------------------------------
// QKV projection: per (m-tile, head, proj) block computes a 128x64 tile of
// C = X_g [8192 x 768] @ W_h [768 x 64] + bias, writing into g_Q/g_K/g_V.
// 256 threads, 8x4 micro-tile, BK=16.
// ---------------------------------------------------------------------------
__global__ __launch_bounds__(256) void qkv_proj_kernel(
    const float* __restrict__ x1, const float* __restrict__ x2, const float* __restrict__ x3,
    const float* __restrict__ Wq, const float* __restrict__ bq,
    const float* __restrict__ Wk, const float* __restrict__ bk,
    const float* __restrict__ Wv, const float* __restrict__ bv)
{
    const int mt = blockIdx.x;   // 0..63  (8192 / 128)
    const int h  = blockIdx.y;   // 0..11
    const int p  = blockIdx.z;   // 0:q 1:k 2:v
    const int g  = h >> 2;

    const float* X    = (g == 0) ? x1 : (g == 1) ? x2 : x3;
    const float* W    = ((p == 0) ? Wq : (p == 1) ? Wk : Wv) + (size_t)h * Hdim * Ddim;
    const float* bias = ((p == 0) ? bq : (p == 1) ? bk : bv) + h * Ddim;
    float* Obuf       = (p == 0) ? g_Q : (p == 1) ? g_K : g_V;

    __shared__ float As[16][132];  // [k][m], padded pitch
    __shared__ float Bs[16][64];   // [k][n]

    const int tid = threadIdx.x;
    const int tm = tid >> 4;        // 0..15, rows tm*8 .. tm*8+7
    const int tn = tid & 15;        // 0..15, cols tn*4 .. tn*4+3
    const int m0 = mt * 128;

    const int arow = tid >> 2;          // 0..63
    const int akc  = (tid & 3) * 4;     // k offset 0,4,8,12

    float acc[8][4];
#pragma unroll
    for (int i = 0; i < 8; i++)
#pragma unroll
        for (int j = 0; j < 4; j++) acc[i][j] = 0.0f;

    for (int k0 = 0; k0 < Hdim; k0 += 16) {
        // Load A tile (transposed into smem)
#pragma unroll
        for (int rp = 0; rp < 2; rp++) {
            int r = arow + rp * 64;
            float4 v = *(const float4*)&X[(size_t)(m0 + r) * Hdim + k0 + akc];
            As[akc + 0][r] = v.x;
            As[akc + 1][r] = v.y;
            As[akc + 2][r] = v.z;
            As[akc + 3][r] = v.w;
        }
        // Load B tile
        {
            int kk = tid >> 4;
            int d  = (tid & 15) * 4;
            *(float4*)&Bs[kk][d] = *(const float4*)&W[(size_t)(k0 + kk) * Ddim + d];
        }
        __syncthreads();

#pragma unroll
        for (int kk = 0; kk < 16; kk++) {
            float a8[8], b4[4];
            *(float4*)&a8[0] = *(const float4*)&As[kk][tm * 8];
            *(float4*)&a8[4] = *(const float4*)&As[kk][tm * 8 + 4];
            *(float4*)&b4[0] = *(const float4*)&Bs[kk][tn * 4];
#pragma unroll
            for (int i = 0; i < 8; i++)
#pragma unroll
                for (int j = 0; j < 4; j++)
                    acc[i][j] += a8[i] * b4[j];
        }
        __syncthreads();
    }

    // Epilogue: bias add, write to [B, NH, S, D]
    float bb[4];
    *(float4*)&bb[0] = *(const float4*)&bias[tn * 4];
#pragma unroll
    for (int i = 0; i < 8; i++) {
        int row = m0 + tm * 8 + i;           // 0..8191 = b*2048 + s
        int b_  = row >> 11;
        int s_  = row & 2047;
        float4 o;
        o.x = acc[i][0] + bb[0];
        o.y = acc[i][1] + bb[1];
        o.z = acc[i][2] + bb[2];
        o.w = acc[i][3] + bb[3];
        *(float4*)&Obuf[((size_t)(b_ * NHdim + h) * Sdim + s_) * Ddim + tn * 4] = o;
    }
}

// ---------------------------------------------------------------------------
// Flash attention, fp32. One block per (q-tile of 64 rows, b*NH+h).
// 256 threads as 16x16 grid; each thread owns a 4x4 micro-tile for both the
// score GEMM (rows x keys) and the PV GEMM (rows x dims). K stored transposed
// in smem; P aliases the K buffer. Static smem = 48KB exactly.
// ---------------------------------------------------------------------------
__global__ __launch_bounds__(256) void attn_kernel(float* __restrict__ out)
{
    __shared__ float Qs[64 * 64];   // [r][d], pre-scaled by SCALE*log2(e)
    __shared__ float KP[64 * 64];   // K transposed [d][c], then P [r][c]
    __shared__ float Vs[64 * 64];   // [c][d]

    const int qt  = blockIdx.x;     // 0..31
    const int bh  = blockIdx.y;     // 0..47  (b*NH + h)
    const int tid = threadIdx.x;
    const int rg  = tid >> 4;       // 0..15
    const int cg  = tid & 15;       // 0..15
    const int r0  = rg * 4;
    const int c0  = cg * 4;

    const float* Qp = g_Q + (size_t)bh * Sdim * Ddim + (size_t)qt * 64 * Ddim;
    const float* Kp = g_K + (size_t)bh * Sdim * Ddim;
    const float* Vp = g_V + (size_t)bh * Sdim * Ddim;

    // Load Q tile, fold in scale * log2(e) so we can use exp2f.
    const float qscale = ATT_SCALE * LOG2E;
    for (int i = tid; i < 1024; i += 256) {
        float4 v = ((const float4*)Qp)[i];
        v.x *= qscale; v.y *= qscale; v.z *= qscale; v.w *= qscale;
        ((float4*)Qs)[i] = v;
    }

    float m_[4], l_[4], o_[4][4];
#pragma unroll
    for (int i = 0; i < 4; i++) {
        m_[i] = -1e30f;
        l_[i] = 0.0f;
#pragma unroll
        for (int j = 0; j < 4; j++) o_[i][j] = 0.0f;
    }

    for (int kt = 0; kt < 32; kt++) {
        const float* Kt = Kp + (size_t)kt * 64 * Ddim;
        const float* Vt = Vp + (size_t)kt * 64 * Ddim;

        // V: straight coalesced copy
        for (int i = tid; i < 1024; i += 256)
            ((float4*)Vs)[i] = ((const float4*)Vt)[i];
        // K: transposed store (c-fast lanes -> conflict-free STS)
        for (int idx = tid; idx < 1024; idx += 256) {
            int c  = idx & 63;
            int db = idx >> 6;       // 0..15
            float4 v = *(const float4*)&Kt[(size_t)c * Ddim + db * 4];
            KP[(db * 4 + 0) * 64 + c] = v.x;
            KP[(db * 4 + 1) * 64 + c] = v.y;
            KP[(db * 4 + 2) * 64 + c] = v.z;
            KP[(db * 4 + 3) * 64 + c] = v.w;
        }
        __syncthreads();

        // Scores: s[i][j] = sum_d Qs[r0+i][d] * K[c0+j][d]
        float s[4][4];
#pragma unroll
        for (int i = 0; i < 4; i++)
#pragma unroll
            for (int j = 0; j < 4; j++) s[i][j] = 0.0f;

#pragma unroll
        for (int d = 0; d < 64; d += 4) {
            float qf[4][4], kf[4][4];
#pragma unroll
            for (int i = 0; i < 4; i++)
                *(float4*)&qf[i][0] = *(const float4*)&Qs[(r0 + i) * 64 + d];
#pragma unroll
            for (int w = 0; w < 4; w++)
                *(float4*)&kf[w][0] = *(const float4*)&KP[(d + w) * 64 + c0];
#pragma unroll
            for (int i = 0; i < 4; i++)
#pragma unroll
                for (int j = 0; j < 4; j++)
#pragma unroll
                    for (int w = 0; w < 4; w++)
                        s[i][j] += qf[i][w] * kf[w][j];
        }
        __syncthreads();  // all reads of KP (K^T) complete

        // Online softmax update; write P into KP
#pragma unroll
        for (int i = 0; i < 4; i++) {
            float rmax = fmaxf(fmaxf(s[i][0], s[i][1]), fmaxf(s[i][2], s[i][3]));
#pragma unroll
            for (int mk = 8; mk >= 1; mk >>= 1)
                rmax = fmaxf(rmax, __shfl_xor_sync(0xffffffffu, rmax, mk));
            float mnew = fmaxf(m_[i], rmax);
            float corr = exp2f(m_[i] - mnew);
            m_[i] = mnew;
            float p0 = exp2f(s[i][0] - mnew);
            float p1 = exp2f(s[i][1] - mnew);
            float p2 = exp2f(s[i][2] - mnew);
            float p3 = exp2f(s[i][3] - mnew);
            float rsum = p0 + p1 + p2 + p3;
#pragma unroll
            for (int mk = 8; mk >= 1; mk >>= 1)
                rsum += __shfl_xor_sync(0xffffffffu, rsum, mk);
            l_[i] = l_[i] * corr + rsum;
#pragma unroll
            for (int j = 0; j < 4; j++) o_[i][j] *= corr;
            float4 p4 = make_float4(p0, p1, p2, p3);
            *(float4*)&KP[(r0 + i) * 64 + c0] = p4;
        }
        __syncthreads();  // P visible to all

        // PV: o[i][j] += sum_c P[r0+i][c] * V[c][d0+j], d0 = c0
#pragma unroll
        for (int c = 0; c < 64; c += 4) {
            float pf[4][4], vf[4][4];
#pragma unroll
            for (int i = 0; i < 4; i++)
                *(float4*)&pf[i][0] = *(const float4*)&KP[(r0 + i) * 64 + c];
#pragma unroll
            for (int w = 0; w < 4; w++)
                *(float4*)&vf[w][0] = *(const float4*)&Vs[(c + w) * 64 + c0];
#pragma unroll
            for (int i = 0; i < 4; i++)
#pragma unroll
                for (int j = 0; j < 4; j++)
#pragma unroll
                    for (int w = 0; w < 4; w++)
                        o_[i][j] += pf[i][w] * vf[w][j];
        }
        __syncthreads();  // protect KP/Vs before next tile load
    }

    // Write out: out[b][s][h*64 + d]
    const int b_ = bh / NHdim;
    const int h_ = bh % NHdim;
#pragma unroll
    for (int i = 0; i < 4; i++) {
        float inv = 1.0f / l_[i];
        int srow = qt * 64 + r0 + i;
        float4 o4;
        o4.x = o_[i][0] * inv;
        o4.y = o_[i][1] * inv;
        o4.z = o_[i][2] * inv;
        o4.w = o_[i][3] * inv;
        *(float4*)&out[((size_t)b_ * Sdim + srow) * (NHdim * Ddim) + h_ * Ddim + c0] = o4;
    }
}

extern "C" void kernel_launch(void* const* d_in, const int* in_sizes, int n_in,
                              void* d_out, int out_size)
{
    const float* e1 = (const float*)d_in[0];
    const float* e2 = (const float*)d_in[1];
    const float* e3 = (const float*)d_in[2];
    const float* Wq = (const float*)d_in[3];
    const float* bq = (const float*)d_in[4];
    const float* Wk = (const float*)d_in[5];
    const float* bk = (const float*)d_in[6];
    const float* Wv = (const float*)d_in[7];
    const float* bv = (const float*)d_in[8];
    float* out = (float*)d_out;

    qkv_proj_kernel<<<dim3(64, 12, 3), 256>>>(e1, e2, e3, Wq, bq, Wk, bk, Wv, bv);
    attn_kernel<<<dim3(32, 48), 256>>>(out);
}

// round 2
// speedup vs baseline: 3.0866x; 3.0866x over previous
#include <cuda_runtime.h>
#include <math.h>
#include <stdint.h>

#define Bdim 4
#define Sdim 2048
#define Hdim 768
#define NHdim 12
#define Ddim 64
#define ATT_SCALE 0.125f
#define LOG2E 1.4426950408889634f

// Scratch: Q/K/V in [B, NH, S, D] fp32.
__device__ float g_Q[Bdim * NHdim * Sdim * Ddim];
__device__ float g_K[Bdim * NHdim * Sdim * Ddim];
__device__ float g_V[Bdim * NHdim * Sdim * Ddim];

__device__ __forceinline__ uint32_t f2tf(float x) {
    uint32_t r;
    asm("cvt.rna.tf32.f32 %0, %1;" : "=r"(r) : "f"(x));
    return r;
}

__device__ __forceinline__ float ex2(float x) {
    float r;
    asm("ex2.approx.ftz.f32 %0, %1;" : "=f"(r) : "f"(x));
    return r;
}

// D = A(m16k8,row) * B(k8n8,col) + C, tf32 inputs, f32 accum.
__device__ __forceinline__ void mma_tf32(float d[4], const uint32_t a[4],
                                         uint32_t b0, uint32_t b1,
                                         const float c[4]) {
    asm("mma.sync.aligned.m16n8k8.row.col.f32.tf32.tf32.f32 "
        "{%0,%1,%2,%3}, {%4,%5,%6,%7}, {%8,%9}, {%10,%11,%12,%13};"
        : "=f"(d[0]), "=f"(d[1]), "=f"(d[2]), "=f"(d[3])
        : "r"(a[0]), "r"(a[1]), "r"(a[2]), "r"(a[3]),
          "r"(b0), "r"(b1),
          "f"(c[0]), "f"(c[1]), "f"(c[2]), "f"(c[3]));
}

// ---------------------------------------------------------------------------
// QKV projection (tf32 tensor cores): per block a 128x64 tile of
// C = X_g [8192 x 768] @ W_h [768 x 64] + bias -> g_Q/g_K/g_V.
// 256 threads = 8 warps in a 4(m) x 2(n) grid; warp tile 32x32.
// ---------------------------------------------------------------------------
#define XPITCH 36
#define WPITCH 72

__global__ __launch_bounds__(256) void qkv_proj_kernel(
    const float* __restrict__ x1, const float* __restrict__ x2, const float* __restrict__ x3,
    const float* __restrict__ Wq, const float* __restrict__ bq,
    const float* __restrict__ Wk, const float* __restrict__ bk,
    const float* __restrict__ Wv, const float* __restrict__ bv)
{
    __shared__ uint32_t Xs[128 * XPITCH];
    __shared__ uint32_t Ws[32 * WPITCH];

    const int mt = blockIdx.x;   // 0..63
    const int h  = blockIdx.y;   // 0..11
    const int p  = blockIdx.z;   // 0:q 1:k 2:v
    const int g_ = h >> 2;

    const float* X    = (g_ == 0) ? x1 : (g_ == 1) ? x2 : x3;
    const float* W    = ((p == 0) ? Wq : (p == 1) ? Wk : Wv) + (size_t)h * Hdim * Ddim;
    const float* bias = ((p == 0) ? bq : (p == 1) ? bk : bv) + h * Ddim;
    float* Obuf       = (p == 0) ? g_Q : (p == 1) ? g_K : g_V;

    const int tid  = threadIdx.x;
    const int w    = tid >> 5;
    const int lane = tid & 31;
    const int g    = lane >> 2;   // groupID
    const int t    = lane & 3;    // threadID_in_group
    const int wm   = w & 3;       // m-block (32 rows)
    const int wn   = w >> 2;      // n-block (32 cols)
    const int m0   = mt * 128;

    float C[2][4][4];
#pragma unroll
    for (int ms = 0; ms < 2; ms++)
#pragma unroll
        for (int f = 0; f < 4; f++)
#pragma unroll
            for (int j = 0; j < 4; j++) C[ms][f][j] = 0.0f;

    for (int k0 = 0; k0 < Hdim; k0 += 32) {
        // X tile: 128 rows x 32 cols
#pragma unroll
        for (int i = tid; i < 1024; i += 256) {
            int r = i >> 3, c = (i & 7) * 4;
            float4 v = *(const float4*)&X[(size_t)(m0 + r) * Hdim + k0 + c];
            uint4 u = make_uint4(f2tf(v.x), f2tf(v.y), f2tf(v.z), f2tf(v.w));
            *(uint4*)&Xs[r * XPITCH + c] = u;
        }
        // W tile: 32 rows(k) x 64 cols
#pragma unroll
        for (int i = tid; i < 512; i += 256) {
            int kr = i >> 4, c = (i & 15) * 4;
            float4 v = *(const float4*)&W[(size_t)(k0 + kr) * Ddim + c];
            uint4 u = make_uint4(f2tf(v.x), f2tf(v.y), f2tf(v.z), f2tf(v.w));
            *(uint4*)&Ws[kr * WPITCH + c] = u;
        }
        __syncthreads();

#pragma unroll
        for (int kk = 0; kk < 4; kk++) {
            uint32_t a[2][4];
#pragma unroll
            for (int ms = 0; ms < 2; ms++) {
                int r = wm * 32 + ms * 16;
                a[ms][0] = Xs[(r + g) * XPITCH + kk * 8 + t];
                a[ms][1] = Xs[(r + g + 8) * XPITCH + kk * 8 + t];
                a[ms][2] = Xs[(r + g) * XPITCH + kk * 8 + t + 4];
                a[ms][3] = Xs[(r + g + 8) * XPITCH + kk * 8 + t + 4];
            }
#pragma unroll
            for (int f = 0; f < 4; f++) {
                uint32_t b0 = Ws[(kk * 8 + t) * WPITCH + wn * 32 + f * 8 + g];
                uint32_t b1 = Ws[(kk * 8 + t + 4) * WPITCH + wn * 32 + f * 8 + g];
                mma_tf32(C[0][f], a[0], b0, b1, C[0][f]);
                mma_tf32(C[1][f], a[1], b0, b1, C[1][f]);
            }
        }
        __syncthreads();
    }

    // Epilogue: bias + store to [B, NH, S, D]
#pragma unroll
    for (int ms = 0; ms < 2; ms++) {
#pragma unroll
        for (int f = 0; f < 4; f++) {
            int col = wn * 32 + f * 8 + 2 * t;
            float b0 = bias[col], b1 = bias[col + 1];
#pragma unroll
            for (int hl = 0; hl < 2; hl++) {
                int row = m0 + wm * 32 + ms * 16 + g + hl * 8;
                int b_ = row >> 11, s_ = row & 2047;
                float2 o;
                o.x = C[ms][f][hl * 2 + 0] + b0;
                o.y = C[ms][f][hl * 2 + 1] + b1;
                *(float2*)&Obuf[((size_t)(b_ * NHdim + h) * Sdim + s_) * Ddim + col] = o;
            }
        }
    }
}

// ---------------------------------------------------------------------------
// Flash attention, tf32 tensor cores. BQ=64, BK=64.
// 128 threads = 4 warps; warp handles 16 rows x all 64 cols.
// Q A-frags in registers for all 32 K-tiles; P stays in registers
// (C-frag -> A-frag via shfl butterfly).
// ---------------------------------------------------------------------------
#define KPITCH 76
#define VPITCH 72

__global__ __launch_bounds__(128) void attn_kernel(float* __restrict__ out)
{
    __shared__ uint32_t Ks[64 * KPITCH];   // 19456 B
    __shared__ uint32_t Vs[64 * VPITCH];   // 18432 B

    const int qt   = blockIdx.x;     // 0..31
    const int bh   = blockIdx.y;     // 0..47
    const int tid  = threadIdx.x;
    const int w    = tid >> 5;       // 0..3
    const int lane = tid & 31;
    const int g    = lane >> 2;
    const int t    = lane & 3;

    const float* Qp = g_Q + ((size_t)bh * Sdim + qt * 64) * Ddim;
    const float* Kp = g_K + (size_t)bh * Sdim * Ddim;
    const float* Vp = g_V + (size_t)bh * Sdim * Ddim;

    // Prologue: stage scaled Q into Vs, pull A-frags into registers.
    const float qs = ATT_SCALE * LOG2E;
#pragma unroll
    for (int i = tid; i < 1024; i += 128) {
        float4 v = ((const float4*)Qp)[i];
        int r = i >> 4, c = (i & 15) * 4;
        uint4 u = make_uint4(f2tf(v.x * qs), f2tf(v.y * qs), f2tf(v.z * qs), f2tf(v.w * qs));
        *(uint4*)&Vs[r * VPITCH + c] = u;
    }
    __syncthreads();

    uint32_t qa[8][4];
#pragma unroll
    for (int kk = 0; kk < 8; kk++) {
        int rlo = w * 16 + g, rhi = rlo + 8;
        qa[kk][0] = Vs[rlo * VPITCH + kk * 8 + t];
        qa[kk][1] = Vs[rhi * VPITCH + kk * 8 + t];
        qa[kk][2] = Vs[rlo * VPITCH + kk * 8 + t + 4];
        qa[kk][3] = Vs[rhi * VPITCH + kk * 8 + t + 4];
    }
    __syncthreads();

    float mlo = -1e30f, mhi = -1e30f, llo = 0.0f, lhi = 0.0f;
    float O[8][4];
#pragma unroll
    for (int f = 0; f < 8; f++)
#pragma unroll
        for (int j = 0; j < 4; j++) O[f][j] = 0.0f;

    for (int kt = 0; kt < 32; kt++) {
        const float* Kt = Kp + (size_t)kt * 64 * Ddim;
        const float* Vt = Vp + (size_t)kt * 64 * Ddim;
#pragma unroll
        for (int i = tid; i < 1024; i += 128) {
            int r = i >> 4, c = (i & 15) * 4;
            float4 kv = ((const float4*)Kt)[i];
            *(uint4*)&Ks[r * KPITCH + c] =
                make_uint4(f2tf(kv.x), f2tf(kv.y), f2tf(kv.z), f2tf(kv.w));
            float4 vv = ((const float4*)Vt)[i];
            *(uint4*)&Vs[r * VPITCH + c] =
                make_uint4(f2tf(vv.x), f2tf(vv.y), f2tf(vv.z), f2tf(vv.w));
        }
        __syncthreads();

        // Scores: S[f] covers cols 8f..8f+7 for this warp's 16 rows.
        float S[8][4];
#pragma unroll
        for (int f = 0; f < 8; f++)
#pragma unroll
            for (int j = 0; j < 4; j++) S[f][j] = 0.0f;

#pragma unroll
        for (int kk = 0; kk < 8; kk++) {
#pragma unroll
            for (int f = 0; f < 8; f++) {
                uint32_t b0 = Ks[(f * 8 + g) * KPITCH + kk * 8 + t];
                uint32_t b1 = Ks[(f * 8 + g) * KPITCH + kk * 8 + t + 4];
                mma_tf32(S[f], qa[kk], b0, b1, S[f]);
            }
        }

        // Online softmax (warp-local rows).
        float mx0 = -1e30f, mx1 = -1e30f;
#pragma unroll
        for (int f = 0; f < 8; f++) {
            mx0 = fmaxf(mx0, fmaxf(S[f][0], S[f][1]));
            mx1 = fmaxf(mx1, fmaxf(S[f][2], S[f][3]));
        }
        mx0 = fmaxf(mx0, __shfl_xor_sync(0xffffffffu, mx0, 1));
        mx0 = fmaxf(mx0, __shfl_xor_sync(0xffffffffu, mx0, 2));
        mx1 = fmaxf(mx1, __shfl_xor_sync(0xffffffffu, mx1, 1));
        mx1 = fmaxf(mx1, __shfl_xor_sync(0xffffffffu, mx1, 2));

        float mn0 = fmaxf(mlo, mx0), mn1 = fmaxf(mhi, mx1);
        float c0 = ex2(mlo - mn0), c1 = ex2(mhi - mn1);
        mlo = mn0; mhi = mn1;

        float rs0 = 0.0f, rs1 = 0.0f;
#pragma unroll
        for (int f = 0; f < 8; f++) {
            S[f][0] = ex2(S[f][0] - mn0);
            S[f][1] = ex2(S[f][1] - mn0);
            S[f][2] = ex2(S[f][2] - mn1);
            S[f][3] = ex2(S[f][3] - mn1);
            rs0 += S[f][0] + S[f][1];
            rs1 += S[f][2] + S[f][3];
            O[f][0] *= c0; O[f][1] *= c0;
            O[f][2] *= c1; O[f][3] *= c1;
        }
        rs0 += __shfl_xor_sync(0xffffffffu, rs0, 1);
        rs0 += __shfl_xor_sync(0xffffffffu, rs0, 2);
        rs1 += __shfl_xor_sync(0xffffffffu, rs1, 1);
        rs1 += __shfl_xor_sync(0xffffffffu, rs1, 2);
        llo = llo * c0 + rs0;
        lhi = lhi * c1 + rs1;

        // PV: A-frag kk is P's key-block kk; convert C-layout -> A-layout
        // via shfl (cols {2t,2t+1} -> {t,t+4}), then mma over all f.
#pragma unroll
        for (int kk = 0; kk < 8; kk++) {
            int src  = (g << 2) | (t >> 1);
            int src2 = src + 2;
            float lo0a = __shfl_sync(0xffffffffu, S[kk][0], src);
            float lo0b = __shfl_sync(0xffffffffu, S[kk][1], src);
            float hi0a = __shfl_sync(0xffffffffu, S[kk][2], src);
            float hi0b = __shfl_sync(0xffffffffu, S[kk][3], src);
            float lo1a = __shfl_sync(0xffffffffu, S[kk][0], src2);
            float lo1b = __shfl_sync(0xffffffffu, S[kk][1], src2);
            float hi1a = __shfl_sync(0xffffffffu, S[kk][2], src2);
            float hi1b = __shfl_sync(0xffffffffu, S[kk][3], src2);
            bool odd = (t & 1);
            uint32_t pa[4];
            pa[0] = f2tf(odd ? lo0b : lo0a);   // (row g,   key t)
            pa[1] = f2tf(odd ? hi0b : hi0a);   // (row g+8, key t)
            pa[2] = f2tf(odd ? lo1b : lo1a);   // (row g,   key t+4)
            pa[3] = f2tf(odd ? hi1b : hi1a);   // (row g+8, key t+4)
#pragma unroll
            for (int f = 0; f < 8; f++) {
                uint32_t b0 = Vs[(kk * 8 + t) * VPITCH + f * 8 + g];
                uint32_t b1 = Vs[(kk * 8 + t + 4) * VPITCH + f * 8 + g];
                mma_tf32(O[f], pa, b0, b1, O[f]);
            }
        }
        __syncthreads();
    }

    // Epilogue: out[b][s][h*64 + d]
    const int b_ = bh / NHdim;
    const int h_ = bh % NHdim;
    float inv0 = 1.0f / llo, inv1 = 1.0f / lhi;
#pragma unroll
    for (int f = 0; f < 8; f++) {
        int col = f * 8 + 2 * t;
#pragma unroll
        for (int hl = 0; hl < 2; hl++) {
            int row = qt * 64 + w * 16 + g + hl * 8;
            float inv = hl ? inv1 : inv0;
            float2 o;
            o.x = O[f][hl * 2 + 0] * inv;
            o.y = O[f][hl * 2 + 1] * inv;
            *(float2*)&out[((size_t)b_ * Sdim + row) * (NHdim * Ddim) + h_ * Ddim + col] = o;
        }
    }
}

extern "C" void kernel_launch(void* const* d_in, const int* in_sizes, int n_in,
                              void* d_out, int out_size)
{
    const float* e1 = (const float*)d_in[0];
    const float* e2 = (const float*)d_in[1];
    const float* e3 = (const float*)d_in[2];
    const float* Wq = (const float*)d_in[3];
    const float* bq = (const float*)d_in[4];
    const float* Wk = (const float*)d_in[5];
    const float* bk = (const float*)d_in[6];
    const float* Wv = (const float*)d_in[7];
    const float* bv = (const float*)d_in[8];
    float* out = (float*)d_out;

    qkv_proj_kernel<<<dim3(64, 12, 3), 256>>>(e1, e2, e3, Wq, bq, Wk, bk, Wv, bv);
    attn_kernel<<<dim3(32, 48), 128>>>(out);
}

// round 3
// speedup vs baseline: 3.0874x; 1.0002x over previous
#include <cuda_runtime.h>
#include <math.h>
#include <stdint.h>

#define Bdim 4
#define Sdim 2048
#define Hdim 768
#define NHdim 12
#define Ddim 64
#define ATT_SCALE 0.125f
#define LOG2E 1.4426950408889634f

// Scratch: Q/K/V in [B, NH, S, D] fp32.
__device__ float g_Q[Bdim * NHdim * Sdim * Ddim];
__device__ float g_K[Bdim * NHdim * Sdim * Ddim];
__device__ float g_V[Bdim * NHdim * Sdim * Ddim];

__device__ __forceinline__ uint32_t f2tf(float x) {
    uint32_t r;
    asm("cvt.rna.tf32.f32 %0, %1;" : "=r"(r) : "f"(x));
    return r;
}

__device__ __forceinline__ float ex2(float x) {
    float r;
    asm("ex2.approx.ftz.f32 %0, %1;" : "=f"(r) : "f"(x));
    return r;
}

// D = A(m16k8,row) * B(k8n8,col) + C, tf32 inputs, f32 accum.
__device__ __forceinline__ void mma_tf32(float d[4], const uint32_t a[4],
                                         uint32_t b0, uint32_t b1,
                                         const float c[4]) {
    asm("mma.sync.aligned.m16n8k8.row.col.f32.tf32.tf32.f32 "
        "{%0,%1,%2,%3}, {%4,%5,%6,%7}, {%8,%9}, {%10,%11,%12,%13};"
        : "=f"(d[0]), "=f"(d[1]), "=f"(d[2]), "=f"(d[3])
        : "r"(a[0]), "r"(a[1]), "r"(a[2]), "r"(a[3]),
          "r"(b0), "r"(b1),
          "f"(c[0]), "f"(c[1]), "f"(c[2]), "f"(c[3]));
}

// ---------------------------------------------------------------------------
// QKV projection (tf32 tensor cores): per block a 128x64 tile of
// C = X_g [8192 x 768] @ W_h [768 x 64] + bias -> g_Q/g_K/g_V.
// 256 threads = 8 warps in a 4(m) x 2(n) grid; warp tile 32x32.
// ---------------------------------------------------------------------------
#define XPITCH 36
#define WPITCH 72

__global__ __launch_bounds__(256) void qkv_proj_kernel(
    const float* __restrict__ x1, const float* __restrict__ x2, const float* __restrict__ x3,
    const float* __restrict__ Wq, const float* __restrict__ bq,
    const float* __restrict__ Wk, const float* __restrict__ bk,
    const float* __restrict__ Wv, const float* __restrict__ bv)
{
    __shared__ uint32_t Xs[128 * XPITCH];
    __shared__ uint32_t Ws[32 * WPITCH];

    const int mt = blockIdx.x;   // 0..63
    const int h  = blockIdx.y;   // 0..11
    const int p  = blockIdx.z;   // 0:q 1:k 2:v
    const int g_ = h >> 2;

    const float* X    = (g_ == 0) ? x1 : (g_ == 1) ? x2 : x3;
    const float* W    = ((p == 0) ? Wq : (p == 1) ? Wk : Wv) + (size_t)h * Hdim * Ddim;
    const float* bias = ((p == 0) ? bq : (p == 1) ? bk : bv) + h * Ddim;
    float* Obuf       = (p == 0) ? g_Q : (p == 1) ? g_K : g_V;

    const int tid  = threadIdx.x;
    const int w    = tid >> 5;
    const int lane = tid & 31;
    const int g    = lane >> 2;   // groupID
    const int t    = lane & 3;    // threadID_in_group
    const int wm   = w & 3;       // m-block (32 rows)
    const int wn   = w >> 2;      // n-block (32 cols)
    const int m0   = mt * 128;

    float C[2][4][4];
#pragma unroll
    for (int ms = 0; ms < 2; ms++)
#pragma unroll
        for (int f = 0; f < 4; f++)
#pragma unroll
            for (int j = 0; j < 4; j++) C[ms][f][j] = 0.0f;

    for (int k0 = 0; k0 < Hdim; k0 += 32) {
        // X tile: 128 rows x 32 cols
#pragma unroll
        for (int i = tid; i < 1024; i += 256) {
            int r = i >> 3, c = (i & 7) * 4;
            float4 v = *(const float4*)&X[(size_t)(m0 + r) * Hdim + k0 + c];
            uint4 u = make_uint4(f2tf(v.x), f2tf(v.y), f2tf(v.z), f2tf(v.w));
            *(uint4*)&Xs[r * XPITCH + c] = u;
        }
        // W tile: 32 rows(k) x 64 cols
#pragma unroll
        for (int i = tid; i < 512; i += 256) {
            int kr = i >> 4, c = (i & 15) * 4;
            float4 v = *(const float4*)&W[(size_t)(k0 + kr) * Ddim + c];
            uint4 u = make_uint4(f2tf(v.x), f2tf(v.y), f2tf(v.z), f2tf(v.w));
            *(uint4*)&Ws[kr * WPITCH + c] = u;
        }
        __syncthreads();

#pragma unroll
        for (int kk = 0; kk < 4; kk++) {
            uint32_t a[2][4];
#pragma unroll
            for (int ms = 0; ms < 2; ms++) {
                int r = wm * 32 + ms * 16;
                a[ms][0] = Xs[(r + g) * XPITCH + kk * 8 + t];
                a[ms][1] = Xs[(r + g + 8) * XPITCH + kk * 8 + t];
                a[ms][2] = Xs[(r + g) * XPITCH + kk * 8 + t + 4];
                a[ms][3] = Xs[(r + g + 8) * XPITCH + kk * 8 + t + 4];
            }
#pragma unroll
            for (int f = 0; f < 4; f++) {
                uint32_t b0 = Ws[(kk * 8 + t) * WPITCH + wn * 32 + f * 8 + g];
                uint32_t b1 = Ws[(kk * 8 + t + 4) * WPITCH + wn * 32 + f * 8 + g];
                mma_tf32(C[0][f], a[0], b0, b1, C[0][f]);
                mma_tf32(C[1][f], a[1], b0, b1, C[1][f]);
            }
        }
        __syncthreads();
    }

    // Epilogue: bias + store to [B, NH, S, D]
#pragma unroll
    for (int ms = 0; ms < 2; ms++) {
#pragma unroll
        for (int f = 0; f < 4; f++) {
            int col = wn * 32 + f * 8 + 2 * t;
            float b0 = bias[col], b1 = bias[col + 1];
#pragma unroll
            for (int hl = 0; hl < 2; hl++) {
                int row = m0 + wm * 32 + ms * 16 + g + hl * 8;
                int b_ = row >> 11, s_ = row & 2047;
                float2 o;
                o.x = C[ms][f][hl * 2 + 0] + b0;
                o.y = C[ms][f][hl * 2 + 1] + b1;
                *(float2*)&Obuf[((size_t)(b_ * NHdim + h) * Sdim + s_) * Ddim + col] = o;
            }
        }
    }
}

// ---------------------------------------------------------------------------
// Flash attention, tf32 tensor cores. BQ=64, BK=64.
// 128 threads = 4 warps; warp handles 16 rows x all 64 cols.
// Q A-frags in registers for all 32 K-tiles; P stays in registers
// (C-frag -> A-frag via shfl butterfly).
// ---------------------------------------------------------------------------
#define KPITCH 76
#define VPITCH 72

__global__ __launch_bounds__(128) void attn_kernel(float* __restrict__ out)
{
    __shared__ uint32_t Ks[64 * KPITCH];   // 19456 B
    __shared__ uint32_t Vs[64 * VPITCH];   // 18432 B

    const int qt   = blockIdx.x;     // 0..31
    const int bh   = blockIdx.y;     // 0..47
    const int tid  = threadIdx.x;
    const int w    = tid >> 5;       // 0..3
    const int lane = tid & 31;
    const int g    = lane >> 2;
    const int t    = lane & 3;

    const float* Qp = g_Q + ((size_t)bh * Sdim + qt * 64) * Ddim;
    const float* Kp = g_K + (size_t)bh * Sdim * Ddim;
    const float* Vp = g_V + (size_t)bh * Sdim * Ddim;

    // Prologue: stage scaled Q into Vs, pull A-frags into registers.
    const float qs = ATT_SCALE * LOG2E;
#pragma unroll
    for (int i = tid; i < 1024; i += 128) {
        float4 v = ((const float4*)Qp)[i];
        int r = i >> 4, c = (i & 15) * 4;
        uint4 u = make_uint4(f2tf(v.x * qs), f2tf(v.y * qs), f2tf(v.z * qs), f2tf(v.w * qs));
        *(uint4*)&Vs[r * VPITCH + c] = u;
    }
    __syncthreads();

    uint32_t qa[8][4];
#pragma unroll
    for (int kk = 0; kk < 8; kk++) {
        int rlo = w * 16 + g, rhi = rlo + 8;
        qa[kk][0] = Vs[rlo * VPITCH + kk * 8 + t];
        qa[kk][1] = Vs[rhi * VPITCH + kk * 8 + t];
        qa[kk][2] = Vs[rlo * VPITCH + kk * 8 + t + 4];
        qa[kk][3] = Vs[rhi * VPITCH + kk * 8 + t + 4];
    }
    __syncthreads();

    float mlo = -1e30f, mhi = -1e30f, llo = 0.0f, lhi = 0.0f;
    float O[8][4];
#pragma unroll
    for (int f = 0; f < 8; f++)
#pragma unroll
        for (int j = 0; j < 4; j++) O[f][j] = 0.0f;

    for (int kt = 0; kt < 32; kt++) {
        const float* Kt = Kp + (size_t)kt * 64 * Ddim;
        const float* Vt = Vp + (size_t)kt * 64 * Ddim;
#pragma unroll
        for (int i = tid; i < 1024; i += 128) {
            int r = i >> 4, c = (i & 15) * 4;
            float4 kv = ((const float4*)Kt)[i];
            *(uint4*)&Ks[r * KPITCH + c] =
                make_uint4(f2tf(kv.x), f2tf(kv.y), f2tf(kv.z), f2tf(kv.w));
            float4 vv = ((const float4*)Vt)[i];
            *(uint4*)&Vs[r * VPITCH + c] =
                make_uint4(f2tf(vv.x), f2tf(vv.y), f2tf(vv.z), f2tf(vv.w));
        }
        __syncthreads();

        // Scores: S[f] covers cols 8f..8f+7 for this warp's 16 rows.
        float S[8][4];
#pragma unroll
        for (int f = 0; f < 8; f++)
#pragma unroll
            for (int j = 0; j < 4; j++) S[f][j] = 0.0f;

#pragma unroll
        for (int kk = 0; kk < 8; kk++) {
#pragma unroll
            for (int f = 0; f < 8; f++) {
                uint32_t b0 = Ks[(f * 8 + g) * KPITCH + kk * 8 + t];
                uint32_t b1 = Ks[(f * 8 + g) * KPITCH + kk * 8 + t + 4];
                mma_tf32(S[f], qa[kk], b0, b1, S[f]);
            }
        }

        // Online softmax (warp-local rows).
        float mx0 = -1e30f, mx1 = -1e30f;
#pragma unroll
        for (int f = 0; f < 8; f++) {
            mx0 = fmaxf(mx0, fmaxf(S[f][0], S[f][1]));
            mx1 = fmaxf(mx1, fmaxf(S[f][2], S[f][3]));
        }
        mx0 = fmaxf(mx0, __shfl_xor_sync(0xffffffffu, mx0, 1));
        mx0 = fmaxf(mx0, __shfl_xor_sync(0xffffffffu, mx0, 2));
        mx1 = fmaxf(mx1, __shfl_xor_sync(0xffffffffu, mx1, 1));
        mx1 = fmaxf(mx1, __shfl_xor_sync(0xffffffffu, mx1, 2));

        float mn0 = fmaxf(mlo, mx0), mn1 = fmaxf(mhi, mx1);
        float c0 = ex2(mlo - mn0), c1 = ex2(mhi - mn1);
        mlo = mn0; mhi = mn1;

        float rs0 = 0.0f, rs1 = 0.0f;
#pragma unroll
        for (int f = 0; f < 8; f++) {
            S[f][0] = ex2(S[f][0] - mn0);
            S[f][1] = ex2(S[f][1] - mn0);
            S[f][2] = ex2(S[f][2] - mn1);
            S[f][3] = ex2(S[f][3] - mn1);
            rs0 += S[f][0] + S[f][1];
            rs1 += S[f][2] + S[f][3];
            O[f][0] *= c0; O[f][1] *= c0;
            O[f][2] *= c1; O[f][3] *= c1;
        }
        rs0 += __shfl_xor_sync(0xffffffffu, rs0, 1);
        rs0 += __shfl_xor_sync(0xffffffffu, rs0, 2);
        rs1 += __shfl_xor_sync(0xffffffffu, rs1, 1);
        rs1 += __shfl_xor_sync(0xffffffffu, rs1, 2);
        llo = llo * c0 + rs0;
        lhi = lhi * c1 + rs1;

        // PV: A-frag kk is P's key-block kk; convert C-layout -> A-layout
        // via shfl (cols {2t,2t+1} -> {t,t+4}), then mma over all f.
#pragma unroll
        for (int kk = 0; kk < 8; kk++) {
            int src  = (g << 2) | (t >> 1);
            int src2 = src + 2;
            float lo0a = __shfl_sync(0xffffffffu, S[kk][0], src);
            float lo0b = __shfl_sync(0xffffffffu, S[kk][1], src);
            float hi0a = __shfl_sync(0xffffffffu, S[kk][2], src);
            float hi0b = __shfl_sync(0xffffffffu, S[kk][3], src);
            float lo1a = __shfl_sync(0xffffffffu, S[kk][0], src2);
            float lo1b = __shfl_sync(0xffffffffu, S[kk][1], src2);
            float hi1a = __shfl_sync(0xffffffffu, S[kk][2], src2);
            float hi1b = __shfl_sync(0xffffffffu, S[kk][3], src2);
            bool odd = (t & 1);
            uint32_t pa[4];
            pa[0] = f2tf(odd ? lo0b : lo0a);   // (row g,   key t)
            pa[1] = f2tf(odd ? hi0b : hi0a);   // (row g+8, key t)
            pa[2] = f2tf(odd ? lo1b : lo1a);   // (row g,   key t+4)
            pa[3] = f2tf(odd ? hi1b : hi1a);   // (row g+8, key t+4)
#pragma unroll
            for (int f = 0; f < 8; f++) {
                uint32_t b0 = Vs[(kk * 8 + t) * VPITCH + f * 8 + g];
                uint32_t b1 = Vs[(kk * 8 + t + 4) * VPITCH + f * 8 + g];
                mma_tf32(O[f], pa, b0, b1, O[f]);
            }
        }
        __syncthreads();
    }

    // Epilogue: out[b][s][h*64 + d]
    const int b_ = bh / NHdim;
    const int h_ = bh % NHdim;
    float inv0 = 1.0f / llo, inv1 = 1.0f / lhi;
#pragma unroll
    for (int f = 0; f < 8; f++) {
        int col = f * 8 + 2 * t;
#pragma unroll
        for (int hl = 0; hl < 2; hl++) {
            int row = qt * 64 + w * 16 + g + hl * 8;
            float inv = hl ? inv1 : inv0;
            float2 o;
            o.x = O[f][hl * 2 + 0] * inv;
            o.y = O[f][hl * 2 + 1] * inv;
            *(float2*)&out[((size_t)b_ * Sdim + row) * (NHdim * Ddim) + h_ * Ddim + col] = o;
        }
    }
}

extern "C" void kernel_launch(void* const* d_in, const int* in_sizes, int n_in,
                              void* d_out, int out_size)
{
    const float* e1 = (const float*)d_in[0];
    const float* e2 = (const float*)d_in[1];
    const float* e3 = (const float*)d_in[2];
    const float* Wq = (const float*)d_in[3];
    const float* bq = (const float*)d_in[4];
    const float* Wk = (const float*)d_in[5];
    const float* bk = (const float*)d_in[6];
    const float* Wv = (const float*)d_in[7];
    const float* bv = (const float*)d_in[8];
    float* out = (float*)d_out;

    qkv_proj_kernel<<<dim3(64, 12, 3), 256>>>(e1, e2, e3, Wq, bq, Wk, bk, Wv, bv);
    attn_kernel<<<dim3(32, 48), 128>>>(out);
}

// round 5
// speedup vs baseline: 3.9917x; 1.2929x over previous
#include <cuda_runtime.h>
#include <math.h>
#include <stdint.h>

#define Bdim 4
#define Sdim 2048
#define Hdim 768
#define NHdim 12
#define Ddim 64
#define ATT_SCALE 0.125f
#define LOG2E 1.4426950408889634f
#define QSCALE (ATT_SCALE * LOG2E)

// All scratch holds tf32-bit payloads in uint32.
__device__ uint32_t g_Q[Bdim * NHdim * Sdim * Ddim];   // [bh][s][d], pre-scaled
__device__ uint32_t g_K[Bdim * NHdim * Sdim * Ddim];   // [bh][s][d]
__device__ uint32_t g_V[Bdim * NHdim * Sdim * Ddim];   // [bh][s][d]
__device__ uint32_t g_Vt[Bdim * NHdim * Ddim * Sdim];  // [bh][d][s]
__device__ uint32_t g_X[3 * 8192 * Hdim];              // [g][row][k]
__device__ uint32_t g_Wt[3 * NHdim * Ddim * Hdim];     // [p][h][d][k]

__device__ __forceinline__ uint32_t f2tf(float x) {
    uint32_t r;
    asm("cvt.rna.tf32.f32 %0, %1;" : "=r"(r) : "f"(x));
    return r;
}
__device__ __forceinline__ float ex2(float x) {
    float r;
    asm("ex2.approx.ftz.f32 %0, %1;" : "=f"(r) : "f"(x));
    return r;
}
__device__ __forceinline__ void mma_tf32(float d[4], const uint32_t a[4],
                                         uint32_t b0, uint32_t b1) {
    asm("mma.sync.aligned.m16n8k8.row.col.f32.tf32.tf32.f32 "
        "{%0,%1,%2,%3}, {%4,%5,%6,%7}, {%8,%9}, {%0,%1,%2,%3};"
        : "+f"(d[0]), "+f"(d[1]), "+f"(d[2]), "+f"(d[3])
        : "r"(a[0]), "r"(a[1]), "r"(a[2]), "r"(a[3]), "r"(b0), "r"(b1));
}
__device__ __forceinline__ void ldsm4(uint32_t r[4], uint32_t saddr) {
    asm volatile("ldmatrix.sync.aligned.m8n8.x4.shared.b16 {%0,%1,%2,%3}, [%4];"
        : "=r"(r[0]), "=r"(r[1]), "=r"(r[2]), "=r"(r[3]) : "r"(saddr));
}
#define CP16(dst, src) asm volatile("cp.async.cg.shared.global [%0], [%1], 16;" :: "r"(dst), "l"(src))
#define CP_COMMIT()    asm volatile("cp.async.commit_group;")
#define CP_WAIT(n)     asm volatile("cp.async.wait_group %0;" :: "n"(n))

// ---------------------------------------------------------------------------
// Prep 1: embeds -> tf32 bits, [g][8192][768].
// ---------------------------------------------------------------------------
__global__ __launch_bounds__(256) void xconv_kernel(
    const float* __restrict__ x1, const float* __restrict__ x2, const float* __restrict__ x3)
{
    const int g = blockIdx.y;
    const float* src = (g == 0) ? x1 : (g == 1) ? x2 : x3;
    size_t i = ((size_t)blockIdx.x * 256 + threadIdx.x) * 4;
    float4 v = *(const float4*)(src + i);
    uint4 u = make_uint4(f2tf(v.x), f2tf(v.y), f2tf(v.z), f2tf(v.w));
    *(uint4*)&g_X[(size_t)g * 8192 * Hdim + i] = u;
}

// ---------------------------------------------------------------------------
// Prep 2: W [NH][768][64] -> Wt [p][h][64][768] tf32. 32x32 tiles.
// grid (12 h, 3 p, 48 = kt(24)*dt(2)); block (32,8).
// ---------------------------------------------------------------------------
__global__ void wtrans_kernel(
    const float* __restrict__ Wq, const float* __restrict__ Wk, const float* __restrict__ Wv)
{
    __shared__ float T[32][33];
    const int h = blockIdx.x, p = blockIdx.y;
    const int kt = blockIdx.z >> 1, dt = blockIdx.z & 1;
    const float* W = ((p == 0) ? Wq : (p == 1) ? Wk : Wv) + (size_t)h * Hdim * Ddim;
    uint32_t* out = g_Wt + (size_t)(p * NHdim + h) * Ddim * Hdim;
    const int tx = threadIdx.x, ty = threadIdx.y;
    const int k0 = kt * 32, d0 = dt * 32;
#pragma unroll
    for (int j = 0; j < 4; j++)
        T[ty + 8 * j][tx] = W[(size_t)(k0 + ty + 8 * j) * Ddim + d0 + tx];
    __syncthreads();
#pragma unroll
    for (int j = 0; j < 4; j++)
        out[(size_t)(d0 + ty + 8 * j) * Hdim + k0 + tx] = f2tf(T[tx][ty + 8 * j]);
}

// ---------------------------------------------------------------------------
// Prep 3 (after proj): V [bh][2048][64] -> Vt [bh][64][2048] (bit copy).
// grid (48, 64 s-tiles, 2 d-tiles); block (32,8).
// ---------------------------------------------------------------------------
__global__ void vtrans_kernel()
{
    __shared__ uint32_t T[32][33];
    const int bh = blockIdx.x;
    const int s0 = blockIdx.y * 32, d0 = blockIdx.z * 32;
    const int tx = threadIdx.x, ty = threadIdx.y;
    const uint32_t* src = g_V + (size_t)bh * Sdim * Ddim;
    uint32_t* dst = g_Vt + (size_t)bh * Ddim * Sdim;
#pragma unroll
    for (int j = 0; j < 4; j++)
        T[ty + 8 * j][tx] = src[(size_t)(s0 + ty + 8 * j) * Ddim + d0 + tx];
    __syncthreads();
#pragma unroll
    for (int j = 0; j < 4; j++)
        dst[(size_t)(d0 + ty + 8 * j) * Sdim + s0 + tx] = T[tx][ty + 8 * j];
}

// ---------------------------------------------------------------------------
// QKV projection. grid (64 mt, 12 h, 3 p), 256 thr = 8 warps (4m x 2n),
// warp tile 32x32, k-slab 32, cp.async double-buffered. Dynamic smem 55296 B.
// Buffer: Xs 128x36 words, Ws 64x36 words.
// ---------------------------------------------------------------------------
#define PJ_BUF 6912

__global__ __launch_bounds__(256) void qkv_proj_kernel(
    const float* __restrict__ bq, const float* __restrict__ bk, const float* __restrict__ bv)
{
    extern __shared__ uint32_t dsm[];
    const int mt = blockIdx.x, h = blockIdx.y, p = blockIdx.z;
    const int grp = h >> 2;
    const uint32_t* Xg = g_X + ((size_t)grp * 8192 + mt * 128) * Hdim;
    const uint32_t* Wg = g_Wt + (size_t)(p * NHdim + h) * Ddim * Hdim;
    const float* bias = ((p == 0) ? bq : (p == 1) ? bk : bv) + h * Ddim;
    uint32_t* Obuf = (p == 0) ? g_Q : (p == 1) ? g_K : g_V;

    const int tid = threadIdx.x, w = tid >> 5, lane = tid & 31;
    const int g = lane >> 2, t = lane & 3;
    const int wm = w & 3, wn = w >> 2;
    const uint32_t smem0 = (uint32_t)__cvta_generic_to_shared(dsm);

    // ldmatrix lane geometry
    const int rA = (lane & 7) + ((lane >> 3) & 1) * 8;
    const int cA = ((lane >> 4) & 1) * 4;
    const int rB = (lane & 7) + ((lane >> 4) & 1) * 8;
    const int cB = ((lane >> 3) & 1) * 4;

    float C[2][4][4];
#pragma unroll
    for (int ms = 0; ms < 2; ms++)
#pragma unroll
        for (int f = 0; f < 4; f++)
#pragma unroll
            for (int j = 0; j < 4; j++) C[ms][f][j] = 0.0f;

    auto issue = [&](int slab, int buf) {
        uint32_t xb = smem0 + buf * PJ_BUF * 4;
        uint32_t wb = xb + 4608 * 4;
        const int k0 = slab * 32;
#pragma unroll
        for (int n = 0; n < 4; n++) {
            int i = tid + n * 256;
            int r = i >> 3, c4 = (i & 7) * 4;
            CP16(xb + (r * 36 + c4) * 4, Xg + (size_t)r * Hdim + k0 + c4);
        }
#pragma unroll
        for (int n = 0; n < 2; n++) {
            int i = tid + n * 256;
            int r = i >> 3, c4 = (i & 7) * 4;
            CP16(wb + (r * 36 + c4) * 4, Wg + (size_t)r * Hdim + k0 + c4);
        }
        CP_COMMIT();
    };

    issue(0, 0);
    for (int s = 0; s < 24; s++) {
        if (s < 23) { issue(s + 1, (s + 1) & 1); CP_WAIT(1); }
        else        { CP_WAIT(0); }
        __syncthreads();
        uint32_t xb = smem0 + (s & 1) * PJ_BUF * 4;
        uint32_t wb = xb + 4608 * 4;
#pragma unroll
        for (int kk = 0; kk < 4; kk++) {
            uint32_t a[2][4], b[2][4];
#pragma unroll
            for (int ms = 0; ms < 2; ms++)
                ldsm4(a[ms], xb + ((wm * 32 + ms * 16 + rA) * 36 + kk * 8 + cA) * 4);
#pragma unroll
            for (int fp = 0; fp < 2; fp++)
                ldsm4(b[fp], wb + ((wn * 32 + fp * 16 + rB) * 36 + kk * 8 + cB) * 4);
#pragma unroll
            for (int ms = 0; ms < 2; ms++)
#pragma unroll
                for (int f = 0; f < 4; f++)
                    mma_tf32(C[ms][f], a[ms], b[f >> 1][(f & 1) * 2], b[f >> 1][(f & 1) * 2 + 1]);
        }
        __syncthreads();
    }

    // Epilogue: bias, (Q: pre-scale), tf32-round, store bits.
    const int m0 = mt * 128;
#pragma unroll
    for (int ms = 0; ms < 2; ms++)
#pragma unroll
        for (int f = 0; f < 4; f++) {
            int col = wn * 32 + f * 8 + 2 * t;
            float b0 = bias[col], b1 = bias[col + 1];
#pragma unroll
            for (int hl = 0; hl < 2; hl++) {
                int row = m0 + wm * 32 + ms * 16 + g + hl * 8;
                int b_ = row >> 11, s_ = row & 2047;
                float vx = C[ms][f][hl * 2 + 0] + b0;
                float vy = C[ms][f][hl * 2 + 1] + b1;
                if (p == 0) { vx *= QSCALE; vy *= QSCALE; }
                uint2 o = make_uint2(f2tf(vx), f2tf(vy));
                *(uint2*)&Obuf[((size_t)(b_ * NHdim + h) * Sdim + s_) * Ddim + col] = o;
            }
        }
}

// ---------------------------------------------------------------------------
// Flash attention, tf32 + ldmatrix + key-permutation. BQ=64, BK=64.
// 128 thr = 4 warps x (16 rows x 64 cols). Smem: Ks/Vs 64x68 words each.
// ---------------------------------------------------------------------------
__global__ __launch_bounds__(128) void attn_kernel(float* __restrict__ out)
{
    __shared__ uint32_t Ks[64 * 68];
    __shared__ uint32_t Vs[64 * 68];

    const int qt = blockIdx.x, bh = blockIdx.y;
    const int tid = threadIdx.x, w = tid >> 5, lane = tid & 31;
    const int g = lane >> 2, t = lane & 3;

    const int rA = (lane & 7) + ((lane >> 3) & 1) * 8;
    const int cA = ((lane >> 4) & 1) * 4;
    const int rB = (lane & 7) + ((lane >> 4) & 1) * 8;
    const int cB = ((lane >> 3) & 1) * 4;

    const uint32_t* Qg = g_Q + ((size_t)bh * Sdim + qt * 64) * Ddim;
    const uint32_t* Kg = g_K + (size_t)bh * Sdim * Ddim;
    const uint32_t* Vg = g_Vt + (size_t)bh * Ddim * Sdim;
    const uint32_t ksb = (uint32_t)__cvta_generic_to_shared(Ks);
    const uint32_t vsb = (uint32_t)__cvta_generic_to_shared(Vs);

    // Prologue: Q tile through Ks -> A-frags in registers.
#pragma unroll
    for (int n = 0; n < 8; n++) {
        int i = tid + n * 128;
        int r = i >> 4, c4 = (i & 15) * 4;
        CP16(ksb + (r * 68 + c4) * 4, Qg + (size_t)r * Ddim + c4);
    }
    CP_COMMIT(); CP_WAIT(0);
    __syncthreads();
    uint32_t qa[8][4];
#pragma unroll
    for (int kk = 0; kk < 8; kk++)
        ldsm4(qa[kk], ksb + ((w * 16 + rA) * 68 + kk * 8 + cA) * 4);
    __syncthreads();

    float mlo = -1e30f, mhi = -1e30f, llo = 0.0f, lhi = 0.0f;
    float O[8][4];
#pragma unroll
    for (int f = 0; f < 8; f++)
#pragma unroll
        for (int j = 0; j < 4; j++) O[f][j] = 0.0f;

    for (int kt = 0; kt < 32; kt++) {
        // Stage K (rows permuted: key k -> slot ((2k)&7)|(k>>2) within 8-block) and Vt.
#pragma unroll
        for (int n = 0; n < 8; n++) {
            int i = tid + n * 128;
            int r = i >> 4, c4 = (i & 15) * 4;
            int k7 = r & 7;
            int pr = (r & 56) | (((k7 << 1) & 7) | (k7 >> 2));
            CP16(ksb + (pr * 68 + c4) * 4, Kg + (size_t)(kt * 64 + r) * Ddim + c4);
        }
#pragma unroll
        for (int n = 0; n < 8; n++) {
            int i = tid + n * 128;
            int d = i >> 4, c4 = (i & 15) * 4;
            CP16(vsb + (d * 68 + c4) * 4, Vg + (size_t)d * Sdim + kt * 64 + c4);
        }
        CP_COMMIT(); CP_WAIT(0);
        __syncthreads();

        // Scores (cols in permuted key order).
        float S[8][4];
#pragma unroll
        for (int f = 0; f < 8; f++)
#pragma unroll
            for (int j = 0; j < 4; j++) S[f][j] = 0.0f;
#pragma unroll
        for (int kk = 0; kk < 8; kk++) {
            uint32_t b[4][4];
#pragma unroll
            for (int fp = 0; fp < 4; fp++)
                ldsm4(b[fp], ksb + ((fp * 16 + rB) * 68 + kk * 8 + cB) * 4);
#pragma unroll
            for (int f = 0; f < 8; f++)
                mma_tf32(S[f], qa[kk], b[f >> 1][(f & 1) * 2], b[f >> 1][(f & 1) * 2 + 1]);
        }

        // Online softmax (permutation-invariant across cols).
        float mx0 = -1e30f, mx1 = -1e30f;
#pragma unroll
        for (int f = 0; f < 8; f++) {
            mx0 = fmaxf(mx0, fmaxf(S[f][0], S[f][1]));
            mx1 = fmaxf(mx1, fmaxf(S[f][2], S[f][3]));
        }
        mx0 = fmaxf(mx0, __shfl_xor_sync(0xffffffffu, mx0, 1));
        mx0 = fmaxf(mx0, __shfl_xor_sync(0xffffffffu, mx0, 2));
        mx1 = fmaxf(mx1, __shfl_xor_sync(0xffffffffu, mx1, 1));
        mx1 = fmaxf(mx1, __shfl_xor_sync(0xffffffffu, mx1, 2));
        float mn0 = fmaxf(mlo, mx0), mn1 = fmaxf(mhi, mx1);
        float c0 = ex2(mlo - mn0), c1 = ex2(mhi - mn1);
        mlo = mn0; mhi = mn1;

        float rs0 = 0.0f, rs1 = 0.0f;
#pragma unroll
        for (int f = 0; f < 8; f++) {
            S[f][0] = ex2(S[f][0] - mn0);
            S[f][1] = ex2(S[f][1] - mn0);
            S[f][2] = ex2(S[f][2] - mn1);
            S[f][3] = ex2(S[f][3] - mn1);
            rs0 += S[f][0] + S[f][1];
            rs1 += S[f][2] + S[f][3];
            O[f][0] *= c0; O[f][1] *= c0;
            O[f][2] *= c1; O[f][3] *= c1;
        }
        rs0 += __shfl_xor_sync(0xffffffffu, rs0, 1);
        rs0 += __shfl_xor_sync(0xffffffffu, rs0, 2);
        rs1 += __shfl_xor_sync(0xffffffffu, rs1, 1);
        rs1 += __shfl_xor_sync(0xffffffffu, rs1, 2);
        llo = llo * c0 + rs0;
        lhi = lhi * c1 + rs1;

        // PV: score C-frag IS the A-frag thanks to the key permutation.
#pragma unroll
        for (int kk = 0; kk < 8; kk++) {
            uint32_t pa[4];
            pa[0] = f2tf(S[kk][0]);
            pa[1] = f2tf(S[kk][2]);
            pa[2] = f2tf(S[kk][1]);
            pa[3] = f2tf(S[kk][3]);
            uint32_t b[4][4];
#pragma unroll
            for (int fp = 0; fp < 4; fp++)
                ldsm4(b[fp], vsb + ((fp * 16 + rB) * 68 + kk * 8 + cB) * 4);
#pragma unroll
            for (int f = 0; f < 8; f++)
                mma_tf32(O[f], pa, b[f >> 1][(f & 1) * 2], b[f >> 1][(f & 1) * 2 + 1]);
        }
        __syncthreads();
    }

    // Epilogue.
    const int b_ = bh / NHdim;
    const int h_ = bh % NHdim;
    float inv0 = 1.0f / llo, inv1 = 1.0f / lhi;
#pragma unroll
    for (int f = 0; f < 8; f++) {
        int col = f * 8 + 2 * t;
#pragma unroll
        for (int hl = 0; hl < 2; hl++) {
            int row = qt * 64 + w * 16 + g + hl * 8;
            float inv = hl ? inv1 : inv0;
            float2 o;
            o.x = O[f][hl * 2 + 0] * inv;
            o.y = O[f][hl * 2 + 1] * inv;
            *(float2*)&out[((size_t)b_ * Sdim + row) * (NHdim * Ddim) + h_ * Ddim + col] = o;
        }
    }
}

extern "C" void kernel_launch(void* const* d_in, const int* in_sizes, int n_in,
                              void* d_out, int out_size)
{
    const float* e1 = (const float*)d_in[0];
    const float* e2 = (const float*)d_in[1];
    const float* e3 = (const float*)d_in[2];
    const float* Wq = (const float*)d_in[3];
    const float* bq = (const float*)d_in[4];
    const float* Wk = (const float*)d_in[5];
    const float* bk = (const float*)d_in[6];
    const float* Wv = (const float*)d_in[7];
    const float* bv = (const float*)d_in[8];
    float* out = (float*)d_out;

    cudaFuncSetAttribute(qkv_proj_kernel,
                         cudaFuncAttributeMaxDynamicSharedMemorySize, 2 * PJ_BUF * 4);

    xconv_kernel<<<dim3(6144, 3), 256>>>(e1, e2, e3);
    wtrans_kernel<<<dim3(12, 3, 48), dim3(32, 8)>>>(Wq, Wk, Wv);
    qkv_proj_kernel<<<dim3(64, 12, 3), 256, 2 * PJ_BUF * 4>>>(bq, bk, bv);
    vtrans_kernel<<<dim3(48, 64, 2), dim3(32, 8)>>>();
    attn_kernel<<<dim3(32, 48), 128>>>(out);
}